// round 13
// baseline (speedup 1.0000x reference)
#include <cuda_runtime.h>
#include <cuda_bf16.h>
#include <math.h>
#include <stdint.h>
#include <stddef.h>

#define B_ 128
#define H_ 8
#define DK 64
#define C_ 50000
#define D_ 512
#define TILE_C 64
#define NTILE 782          // 782*64 = 50048 >= 50000
#define NTILE_PAD 800
#define NCHUNK 8
#define CHTILES 100        // 8*100 = 800 == NTILE_PAD
#define NITEMS (NTILE * H_)   // 6256
#define NBLK1 444             // 148 SMs * 3 CTAs: exactly one wave

#define COS_M 0.9800665778412416f
#define SIN_M 0.19866933079506122f
#define TH_  (-0.9800665778412416f)
#define MM_  0.039733866159012244f
#define S_   30.0f
#define QS   31500.0f
#define QINV2 1.3739952770371081e-3f
#define S2_   43.280851226668902f
#define S2K_  46.280851226668902f

// ---- pass1 smem layout (bytes) ----
#define OFF_AH 0
#define OFF_AL 16384
#define OFF_BH 32768
#define OFF_BL 40960
#define OFF_RAW 49152      // 16KB raw fp32 tile (cp.async staging)
#define OFF_WINV 65536     // 64 floats
#define OFF_WP   65792     // 256 floats
#define OFF_PS   66816     // 256 floats
#define SMEM1    67840

// ---------------- device scratch ----------------
__device__ __align__(16) __nv_bfloat16 g_Asw[H_ * 16384];
__device__ uint32_t g_Q[(size_t)H_ * NTILE * 8 * 512];      // 102MB
__device__ float g_psum[H_ * NTILE_PAD * B_];
__device__ __align__(16) float g_psum2[B_ * H_ * NCHUNK];
__device__ float g_coslab[B_ * H_];
__device__ int   g_label[B_];

// ---------------- helpers ----------------
__device__ __forceinline__ uint32_t smem_u32(const void* p) {
    uint32_t a;
    asm("{ .reg .u64 t; cvta.to.shared.u64 t, %1; cvt.u32.u64 %0, t; }" : "=r"(a) : "l"(p));
    return a;
}
__device__ __forceinline__ unsigned swz(unsigned by) { return by ^ ((by >> 3) & 0x70); }
__device__ __forceinline__ float ex2a(float x) {
    float y;
    asm("ex2.approx.f32 %0, %1;" : "=f"(y) : "f"(x));
    return y;
}
__device__ __forceinline__ void ldsm4(uint32_t* r, uint32_t addr) {
    asm volatile("ldmatrix.sync.aligned.m8n8.x4.shared.b16 {%0,%1,%2,%3}, [%4];"
                 : "=r"(r[0]), "=r"(r[1]), "=r"(r[2]), "=r"(r[3]) : "r"(addr));
}
__device__ __forceinline__ void mma_bf16(float* d, const uint32_t* a, uint32_t b0, uint32_t b1) {
    asm volatile("mma.sync.aligned.m16n8k16.row.col.f32.bf16.bf16.f32 "
                 "{%0,%1,%2,%3}, {%4,%5,%6,%7}, {%8,%9}, {%0,%1,%2,%3};"
                 : "+f"(d[0]), "+f"(d[1]), "+f"(d[2]), "+f"(d[3])
                 : "r"(a[0]), "r"(a[1]), "r"(a[2]), "r"(a[3]), "r"(b0), "r"(b1));
}
__device__ __forceinline__ uint32_t cvt_bf16x2(float a, float b) {
    uint32_t r;
    asm("cvt.rn.bf16x2.f32 %0, %1, %2;" : "=r"(r) : "f"(b), "f"(a));
    return r;
}
#define CP_COMMIT() asm volatile("cp.async.commit_group;" ::: "memory")
#define CP_WAIT0()  asm volatile("cp.async.wait_group 0;" ::: "memory")

// issue 4 x 16B cp.async chunks of the raw W tile (zero-fill past C_)
__device__ __forceinline__ void cpasync_raw(const float* __restrict__ w, int h, int c0,
                                            uint32_t raw_sm, int tid) {
    #pragma unroll
    for (int j = 0; j < 4; j++) {
        int chunk = tid + 256 * j;
        int k = chunk >> 4;
        int cg = c0 + ((chunk & 15) << 2);
        const float* src = w + ((size_t)(h * DK + k)) * C_ + cg;
        int vf = C_ - cg;
        int bytes = (vf >= 4) ? 16 : ((vf > 0) ? vf * 4 : 0);
        if (bytes == 0) src = w;   // safe address; nothing read
        asm volatile("cp.async.cg.shared.global [%0], [%1], 16, %2;"
                     :: "r"(raw_sm + chunk * 16), "l"(src), "r"(bytes));
    }
}

// ---------------- xnorm (+ label decode in block 0) ----------------
__global__ void k_xnorm(const float* __restrict__ x, const int* __restrict__ raw) {
    __shared__ float wpz[16];
    __shared__ int is64;
    int b = blockIdx.x, t = threadIdx.x;
    if (b == 0 && t == 0) {
        int acc = 0;
        #pragma unroll
        for (int i = 0; i < 64; i++) acc |= raw[2 * i + 1];
        is64 = (acc == 0);
    }
    float v = x[b * D_ + t];
    float s = v * v;
    #pragma unroll
    for (int o = 16; o > 0; o >>= 1) s += __shfl_down_sync(0xffffffffu, s, o);
    if ((t & 31) == 0) wpz[t >> 5] = s;
    __syncthreads();
    if (b == 0 && t < 128) g_label[t] = is64 ? raw[2 * t] : raw[t];
    int h = t >> 6, k = t & 63;
    float ss = wpz[2 * h] + wpz[2 * h + 1];
    float xn = v * (1.0f / fmaxf(sqrtf(ss), 1e-12f));
    __nv_bfloat16 hi = __float2bfloat16(xn);
    __nv_bfloat16 lo = __float2bfloat16(xn - __bfloat162float(hi));
    unsigned by = (unsigned)b * 128u + 2u * (unsigned)k;
    unsigned sw = swz(by);
    g_Asw[h * 16384 + (sw >> 1)] = hi;
    g_Asw[h * 16384 + 8192 + (sw >> 1)] = lo;
}

// ---------------- pass1: persistent, cp.async-pipelined --------------------
__global__ __launch_bounds__(256, 3) void k_pass1(const float* __restrict__ w) {
    extern __shared__ char sm[];
    const int tid = threadIdx.x, warp = tid >> 5, lane = tid & 31;
    uint32_t sb = smem_u32(sm);
    const uint32_t raw_sm = sb + OFF_RAW;

    const int s = (blockIdx.x * NITEMS) / NBLK1;
    const int e = ((blockIdx.x + 1) * NITEMS) / NBLK1;

    // thread-invariant tile coords
    const int wm = warp >> 1, wn = warp & 1;
    const int m0 = wm * 32, n0 = wn * 32;
    const int lrow = lane & 7, lt = lane >> 3;
    const int rowAo = lrow + (lt & 1) * 8;
    const int kbAo = (lt >> 1) * 16;
    const int rowBo = lrow + (lt >> 1) * 8;
    const int kbBo = (lt & 1) * 16;
    const int r0 = m0 + (lane >> 2);
    int labr[4];
    #pragma unroll
    for (int i = 0; i < 4; i++) labr[i] = g_label[r0 + (i >> 1) * 16 + (i & 1) * 8];

    // prologue: A(h0) + raw(t0)
    int h_cur = s / NTILE;
    {
        const uint4* src = (const uint4*)(g_Asw + h_cur * 16384);
        uint4* dst = (uint4*)(sm + OFF_AH);
        #pragma unroll
        for (int i = 0; i < 8; i++) dst[tid + 256 * i] = src[tid + 256 * i];
        cpasync_raw(w, h_cur, (s - h_cur * NTILE) * TILE_C, raw_sm, tid);
        CP_COMMIT();
        CP_WAIT0();
    }
    __syncthreads();

    for (int it = s; it < e; it++) {
        const int h = it / NTILE, t = it - h * NTILE;
        const int c0 = t * TILE_C;

        if (h != h_cur) {   // <=1 time per block (contiguous h-major chunk)
            const uint4* src = (const uint4*)(g_Asw + h * 16384);
            uint4* dst = (uint4*)(sm + OFF_AH);
            #pragma unroll
            for (int i = 0; i < 8; i++) dst[tid + 256 * i] = src[tid + 256 * i];
            h_cur = h;
        }

        // convert raw smem -> bf16 limbs (+ per-col sqnorm)
        {
            int c = tid & 63, kg = tid >> 6;
            bool valid = (c0 + c) < C_;
            const float* raw = (const float*)(sm + OFF_RAW);
            float ss = 0.f;
            #pragma unroll
            for (int i = 0; i < 8; i++) {
                float v0 = raw[(kg * 16 + 2 * i) * 64 + c];
                float v1 = raw[(kg * 16 + 2 * i + 1) * 64 + c];
                if (!valid) { v0 = 0.f; v1 = 0.f; }
                ss = fmaf(v0, v0, ss); ss = fmaf(v1, v1, ss);
                uint32_t hpk = cvt_bf16x2(v0, v1);
                float r0f = v0 - __uint_as_float(hpk << 16);
                float r1f = v1 - __uint_as_float(hpk & 0xFFFF0000u);
                uint32_t lpk = cvt_bf16x2(r0f, r1f);
                unsigned by = (unsigned)c * 128u + (unsigned)(kg * 32 + 4 * i);
                unsigned sw = swz(by);
                *(uint32_t*)(sm + OFF_BH + sw) = hpk;
                *(uint32_t*)(sm + OFF_BL + sw) = lpk;
            }
            ((float*)(sm + OFF_WP))[c * 4 + kg] = ss;
        }
        __syncthreads();                       // S1: A/BH/BL/WP visible, raw free
        if (tid < 64) {
            float* wp = (float*)(sm + OFF_WP);
            ((float*)(sm + OFF_WINV))[tid] =
                1.0f / fmaxf(sqrtf(wp[tid * 4] + wp[tid * 4 + 1] +
                                   wp[tid * 4 + 2] + wp[tid * 4 + 3]), 1e-12f);
        }
        // prefetch next tile's raw weights (overlaps MMA + epilogue)
        if (it + 1 < e) {
            int h2 = (it + 1) / NTILE, t2 = (it + 1) - h2 * NTILE;
            cpasync_raw(w, h2, t2 * TILE_C, raw_sm, tid);
            CP_COMMIT();
        }

        float acc[32];
        #pragma unroll
        for (int i = 0; i < 32; i++) acc[i] = 0.f;

        #pragma unroll
        for (int ks = 0; ks < 4; ks++) {
            uint32_t aH[2][4], aL[2][4];
            #pragma unroll
            for (int mb = 0; mb < 2; mb++) {
                unsigned sw = swz((unsigned)((m0 + mb * 16 + rowAo) * 128 + ks * 32 + kbAo));
                ldsm4(aH[mb], sb + OFF_AH + sw);
                ldsm4(aL[mb], sb + OFF_AL + sw);
            }
            #pragma unroll
            for (int p = 0; p < 2; p++) {
                unsigned sw = swz((unsigned)((n0 + p * 16 + rowBo) * 128 + ks * 32 + kbBo));
                uint32_t bH[4], bL[4];
                ldsm4(bH, sb + OFF_BH + sw);
                ldsm4(bL, sb + OFF_BL + sw);
                #pragma unroll
                for (int mb = 0; mb < 2; mb++) {
                    float* d0 = acc + (mb * 4 + p * 2) * 4;
                    float* d1 = acc + (mb * 4 + p * 2 + 1) * 4;
                    mma_bf16(d0, aH[mb], bH[0], bH[1]);
                    mma_bf16(d1, aH[mb], bH[2], bH[3]);
                    mma_bf16(d0, aH[mb], bL[0], bL[1]);
                    mma_bf16(d1, aH[mb], bL[2], bL[3]);
                    mma_bf16(d0, aL[mb], bH[0], bH[1]);
                    mma_bf16(d1, aL[mb], bH[2], bH[3]);
                }
            }
        }
        __syncthreads();                       // S2: winv visible; MMA done

        // epilogue: cosine -> margin -> quantize int16 -> exp2
        const float* winv = (const float*)(sm + OFF_WINV);
        float* ps = (float*)(sm + OFF_PS);
        float rsum[4] = {0.f, 0.f, 0.f, 0.f};
        const size_t wbase = (((size_t)h * NTILE + t) * 8 + warp) * 512;

        #pragma unroll
        for (int mb = 0; mb < 2; mb++) {
            #pragma unroll
            for (int pn = 0; pn < 4; pn++) {
                int cb = n0 + pn * 8 + (lane & 3) * 2;
                float w0 = winv[cb], w1 = winv[cb + 1];
                int cg = c0 + cb;
                uint2 pk2;
                #pragma unroll
                for (int pr = 0; pr < 2; pr++) {
                    int row = r0 + mb * 16 + pr * 8;
                    int lb = labr[mb * 2 + pr];
                    float v0 = acc[(mb * 4 + pn) * 4 + pr * 2 + 0];
                    float v1 = acc[(mb * 4 + pn) * 4 + pr * 2 + 1];
                    float cos0 = v0 * w0, cos1 = v1 * w1;
                    int qi0 = 0, qi1 = 0;
                    if (cg < C_) {
                        float val = cos0;
                        if (cg == lb) {
                            float sn = sqrtf(fmaxf(1.f - cos0 * cos0, 0.f));
                            float ph = cos0 * COS_M - sn * SIN_M;
                            val = (cos0 > TH_) ? ph : (cos0 - MM_);
                            g_coslab[row * H_ + h] = cos0;
                        }
                        qi0 = __float2int_rn(val * QS);
                        rsum[mb * 2 + pr] += ex2a(fmaf((float)qi0, QINV2, -S2_));
                    }
                    if (cg + 1 < C_) {
                        float val = cos1;
                        if (cg + 1 == lb) {
                            float sn = sqrtf(fmaxf(1.f - cos1 * cos1, 0.f));
                            float ph = cos1 * COS_M - sn * SIN_M;
                            val = (cos1 > TH_) ? ph : (cos1 - MM_);
                            g_coslab[row * H_ + h] = cos1;
                        }
                        qi1 = __float2int_rn(val * QS);
                        rsum[mb * 2 + pr] += ex2a(fmaf((float)qi1, QINV2, -S2_));
                    }
                    uint32_t pk = ((uint32_t)(uint16_t)(short)qi0) |
                                  (((uint32_t)(uint16_t)(short)qi1) << 16);
                    if (pr == 0) pk2.x = pk; else pk2.y = pk;
                }
                *(uint2*)&g_Q[wbase + (size_t)(mb * 4 + pn) * 64 + lane * 2] = pk2;
            }
        }
        #pragma unroll
        for (int i = 0; i < 4; i++) {
            float v = rsum[i];
            v += __shfl_down_sync(0xffffffffu, v, 1);
            v += __shfl_down_sync(0xffffffffu, v, 2);
            if ((lane & 3) == 0)
                ps[(r0 + (i >> 1) * 16 + (i & 1) * 8) * 2 + wn] = v;
        }
        __syncthreads();                       // S3: ps visible
        if (tid < 128)
            g_psum[((size_t)h * NTILE_PAD + t) * B_ + tid] = ps[tid * 2] + ps[tid * 2 + 1];
        if (it + 1 < e) CP_WAIT0();            // next raw tile landed
        __syncthreads();                       // S4: ps reads done; raw ready
    }
}

// ---------------- stage-1 reduction (8 chunks; transposed output) -----------
__global__ void k_sumexp1() {
    int h = blockIdx.x, ch = blockIdx.y, b = threadIdx.x;
    int t0 = ch * CHTILES;
    float s = 0.f;
    #pragma unroll
    for (int t = 0; t < CHTILES; t++)
        s += g_psum[((size_t)h * NTILE_PAD + t0 + t) * B_ + b];
    g_psum2[(b * H_ + h) * NCHUNK + ch] = s;
}

// ---------------- k_out: head-mean of softmax (inline invsum + loss) --------
__global__ __launch_bounds__(256, 5) void k_out(float* __restrict__ out, int write_loss) {
    __shared__ float invs[1024];
    __shared__ float red[256];
    const int tid = threadIdx.x, warp = tid >> 5, lane = tid & 31;
    const int tile = blockIdx.x, mb = blockIdx.y, c0 = tile * TILE_C;

    #pragma unroll
    for (int i = 0; i < 4; i++) {
        int idx = tid + 256 * i;
        const float4* p = (const float4*)&g_psum2[idx * NCHUNK];
        float4 a = p[0], b4 = p[1];
        float ssum = ((a.x + a.y) + (a.z + a.w)) + ((b4.x + b4.y) + (b4.z + b4.w));
        invs[idx] = 1.0f / ssum;
    }
    __syncthreads();

    if (blockIdx.x == 0 && mb == 0) {
        float nll = 0.f;
        #pragma unroll
        for (int i = 0; i < 4; i++) {
            int idx = tid + 256 * i;
            float iv = invs[idx];
            float cos = g_coslab[idx];
            float sn = sqrtf(fmaxf(1.0f - cos * cos, 0.0f));
            float ph = cos * COS_M - sn * SIN_M;
            float val = (cos > TH_) ? ph : (cos - MM_);
            nll += -(S_ * val - S_ + logf(iv));
        }
        red[tid] = nll;
        __syncthreads();
        #pragma unroll
        for (int st = 128; st > 0; st >>= 1) {
            if (tid < st) red[tid] += red[tid + st];
            __syncthreads();
        }
        if (tid == 0 && write_loss)
            out[(size_t)B_ * C_] = red[0] * (1.0f / (B_ * H_));
    }

    const int wm = warp >> 1, wn = warp & 1;
    const int r0 = wm * 32 + mb * 16 + (lane >> 2);
    const int n0 = wn * 32;

    float acc[16];
    #pragma unroll
    for (int i = 0; i < 16; i++) acc[i] = 0.f;

    for (int h = 0; h < H_; h++) {
        const uint32_t* Qp = g_Q + (((size_t)h * NTILE + tile) * 8 + warp) * 512;
        float s0 = invs[r0 * H_ + h];
        float s1 = invs[(r0 + 8) * H_ + h];
        #pragma unroll
        for (int pn = 0; pn < 4; pn++) {
            uint2 pk2 = *(const uint2*)&Qp[(size_t)(mb * 4 + pn) * 64 + lane * 2];
            #pragma unroll
            for (int pr = 0; pr < 2; pr++) {
                uint32_t pk = pr ? pk2.y : pk2.x;
                float q0 = (float)(short)(pk & 0xFFFFu);
                float q1 = (float)(short)(pk >> 16);
                float sv = pr ? s1 : s0;
                float e0 = ex2a(fmaf(q0, QINV2, -S2K_));
                float e1 = ex2a(fmaf(q1, QINV2, -S2K_));
                int ai = pn * 4 + pr * 2;
                acc[ai]     = fmaf(e0, sv, acc[ai]);
                acc[ai + 1] = fmaf(e1, sv, acc[ai + 1]);
            }
        }
    }
    #pragma unroll
    for (int pn = 0; pn < 4; pn++)
        #pragma unroll
        for (int pr = 0; pr < 2; pr++) {
            int row = r0 + pr * 8;
            int cg = c0 + n0 + pn * 8 + (lane & 3) * 2;
            int ai = pn * 4 + pr * 2;
            if (cg + 1 < C_) {
                *(float2*)&out[(size_t)row * C_ + cg] = make_float2(acc[ai], acc[ai + 1]);
            } else if (cg < C_) {
                out[(size_t)row * C_ + cg] = acc[ai];
            }
        }
}

// ---------------- launcher ----------------
extern "C" void kernel_launch(void* const* d_in, const int* in_sizes, int n_in,
                              void* d_out, int out_size) {
    const float* x = (const float*)d_in[0];
    const float* w = (const float*)d_in[1];
    const int*   lab = (const int*)d_in[2];
    float* out = (float*)d_out;
    (void)in_sizes; (void)n_in;

    static int inited = 0;
    if (!inited) {
        cudaFuncSetAttribute(k_pass1, cudaFuncAttributeMaxDynamicSharedMemorySize, SMEM1);
        inited = 1;
    }
    int write_loss = (out_size > B_ * C_) ? 1 : 0;

    k_xnorm<<<B_, D_>>>(x, lab);
    k_pass1<<<NBLK1, 256, SMEM1>>>(w);
    {
        dim3 g2(H_, NCHUNK);
        k_sumexp1<<<g2, B_>>>();
    }
    {
        dim3 g3(NTILE, 2);
        k_out<<<g3, 256>>>(out, write_loss);
    }
}

// round 15
// speedup vs baseline: 1.0453x; 1.0453x over previous
#include <cuda_runtime.h>
#include <cuda_bf16.h>
#include <math.h>
#include <stdint.h>
#include <stddef.h>

#define B_ 128
#define H_ 8
#define DK 64
#define C_ 50000
#define D_ 512
#define TILE_C 64
#define NTILE 782          // 782*64 = 50048 >= 50000
#define NTILE_PAD 800
#define NCHUNK 8
#define CHTILES 100        // 8*100 = 800 == NTILE_PAD

#define COS_M 0.9800665778412416f
#define SIN_M 0.19866933079506122f
#define TH_  (-0.9800665778412416f)
#define MM_  0.039733866159012244f
#define S_   30.0f
#define QS   31500.0f
#define QINV2 1.3739952770371081e-3f
#define S2_   43.280851226668902f
#define S2K_  46.280851226668902f     // 1/8 head-mean folded into exponent

// ---- pass1 smem layout (bytes) ----
#define OFF_AH 0
#define OFF_AL 16384
#define OFF_BH 32768
#define OFF_BL 40960
#define OFF_WINV 49152     // 64 floats
#define OFF_WP   49408     // 256 floats
#define OFF_PS   50432     // 256 floats
#define SMEM1    51456

// ---------------- device scratch ----------------
__device__ __align__(16) __nv_bfloat16 g_Asw[H_ * 16384];
__device__ uint32_t g_Q[(size_t)H_ * NTILE * 8 * 512];      // 102MB
__device__ float g_psum[H_ * NTILE_PAD * B_];
__device__ __align__(16) float g_psum2[B_ * H_ * NCHUNK];   // [(b*8+h)][chunk]
__device__ float g_coslab[B_ * H_];
__device__ int   g_label[B_];

// ---------------- helpers ----------------
__device__ __forceinline__ uint32_t smem_u32(const void* p) {
    uint32_t a;
    asm("{ .reg .u64 t; cvta.to.shared.u64 t, %1; cvt.u32.u64 %0, t; }" : "=r"(a) : "l"(p));
    return a;
}
__device__ __forceinline__ unsigned swz(unsigned by) { return by ^ ((by >> 3) & 0x70); }
__device__ __forceinline__ float ex2a(float x) {
    float y;
    asm("ex2.approx.f32 %0, %1;" : "=f"(y) : "f"(x));
    return y;
}
__device__ __forceinline__ void ldsm4(uint32_t* r, uint32_t addr) {
    asm volatile("ldmatrix.sync.aligned.m8n8.x4.shared.b16 {%0,%1,%2,%3}, [%4];"
                 : "=r"(r[0]), "=r"(r[1]), "=r"(r[2]), "=r"(r[3]) : "r"(addr));
}
__device__ __forceinline__ void mma_bf16(float* d, const uint32_t* a, uint32_t b0, uint32_t b1) {
    asm volatile("mma.sync.aligned.m16n8k16.row.col.f32.bf16.bf16.f32 "
                 "{%0,%1,%2,%3}, {%4,%5,%6,%7}, {%8,%9}, {%0,%1,%2,%3};"
                 : "+f"(d[0]), "+f"(d[1]), "+f"(d[2]), "+f"(d[3])
                 : "r"(a[0]), "r"(a[1]), "r"(a[2]), "r"(a[3]), "r"(b0), "r"(b1));
}
__device__ __forceinline__ uint32_t cvt_bf16x2(float a, float b) {
    uint32_t r;
    asm("cvt.rn.bf16x2.f32 %0, %1, %2;" : "=r"(r) : "f"(b), "f"(a));
    return r;
}

// ---------------- xnorm (+ label decode in block 0) ----------------
__global__ void k_xnorm(const float* __restrict__ x, const int* __restrict__ raw) {
    __shared__ float wpz[16];
    __shared__ int is64;
    int b = blockIdx.x, t = threadIdx.x;
    if (b == 0 && t == 0) {
        int acc = 0;
        #pragma unroll
        for (int i = 0; i < 64; i++) acc |= raw[2 * i + 1];
        is64 = (acc == 0);
    }
    float v = x[b * D_ + t];
    float s = v * v;
    #pragma unroll
    for (int o = 16; o > 0; o >>= 1) s += __shfl_down_sync(0xffffffffu, s, o);
    if ((t & 31) == 0) wpz[t >> 5] = s;
    __syncthreads();
    if (b == 0 && t < 128) g_label[t] = is64 ? raw[2 * t] : raw[t];
    int h = t >> 6, k = t & 63;
    float ss = wpz[2 * h] + wpz[2 * h + 1];
    float xn = v * (1.0f / fmaxf(sqrtf(ss), 1e-12f));
    __nv_bfloat16 hi = __float2bfloat16(xn);
    __nv_bfloat16 lo = __float2bfloat16(xn - __bfloat162float(hi));
    unsigned by = (unsigned)b * 128u + 2u * (unsigned)k;
    unsigned sw = swz(by);
    g_Asw[h * 16384 + (sw >> 1)] = hi;
    g_Asw[h * 16384 + 8192 + (sw >> 1)] = lo;
}

// ---------------- pass1 (R12 champion) ----------------
__global__ __launch_bounds__(256, 3) void k_pass1(const float* __restrict__ w) {
    extern __shared__ char sm[];
    const int tid = threadIdx.x, warp = tid >> 5, lane = tid & 31;
    const int h = blockIdx.y, tile = blockIdx.x, c0 = tile * TILE_C;
    uint32_t sb = smem_u32(sm);

    {
        const uint4* src = (const uint4*)(g_Asw + h * 16384);
        uint4* dst = (uint4*)(sm + OFF_AH);
        #pragma unroll
        for (int i = 0; i < 8; i++) dst[tid + 256 * i] = src[tid + 256 * i];
    }
    {
        int c = tid & 63, kg = tid >> 6;
        int cg = c0 + c;
        bool valid = cg < C_;
        const float* wp0 = w + ((size_t)(h * DK + kg * 16)) * C_ + cg;
        float ss = 0.f;
        #pragma unroll
        for (int i = 0; i < 8; i++) {
            float v0 = valid ? __ldg(wp0 + (size_t)(2 * i) * C_) : 0.f;
            float v1 = valid ? __ldg(wp0 + (size_t)(2 * i + 1) * C_) : 0.f;
            ss = fmaf(v0, v0, ss); ss = fmaf(v1, v1, ss);
            uint32_t hpk = cvt_bf16x2(v0, v1);
            float r0 = v0 - __uint_as_float(hpk << 16);
            float r1 = v1 - __uint_as_float(hpk & 0xFFFF0000u);
            uint32_t lpk = cvt_bf16x2(r0, r1);
            unsigned by = (unsigned)c * 128u + (unsigned)(kg * 32 + 4 * i);
            unsigned sw = swz(by);
            *(uint32_t*)(sm + OFF_BH + sw) = hpk;
            *(uint32_t*)(sm + OFF_BL + sw) = lpk;
        }
        ((float*)(sm + OFF_WP))[c * 4 + kg] = ss;
    }
    __syncthreads();
    if (tid < 64) {
        float* wp = (float*)(sm + OFF_WP);
        ((float*)(sm + OFF_WINV))[tid] =
            1.0f / fmaxf(sqrtf(wp[tid * 4] + wp[tid * 4 + 1] + wp[tid * 4 + 2] + wp[tid * 4 + 3]),
                         1e-12f);
    }

    const int wm = warp >> 1, wn = warp & 1;
    const int m0 = wm * 32, n0 = wn * 32;
    const int lrow = lane & 7, lt = lane >> 3;
    const int rowAo = lrow + (lt & 1) * 8;
    const int kbAo = (lt >> 1) * 16;
    const int rowBo = lrow + (lt >> 1) * 8;
    const int kbBo = (lt & 1) * 16;

    float acc[32];
    #pragma unroll
    for (int i = 0; i < 32; i++) acc[i] = 0.f;

    #pragma unroll
    for (int ks = 0; ks < 4; ks++) {
        uint32_t aH[2][4], aL[2][4];
        #pragma unroll
        for (int mb = 0; mb < 2; mb++) {
            unsigned sw = swz((unsigned)((m0 + mb * 16 + rowAo) * 128 + ks * 32 + kbAo));
            ldsm4(aH[mb], sb + OFF_AH + sw);
            ldsm4(aL[mb], sb + OFF_AL + sw);
        }
        #pragma unroll
        for (int p = 0; p < 2; p++) {
            unsigned sw = swz((unsigned)((n0 + p * 16 + rowBo) * 128 + ks * 32 + kbBo));
            uint32_t bH[4], bL[4];
            ldsm4(bH, sb + OFF_BH + sw);
            ldsm4(bL, sb + OFF_BL + sw);
            #pragma unroll
            for (int mb = 0; mb < 2; mb++) {
                float* d0 = acc + (mb * 4 + p * 2) * 4;
                float* d1 = acc + (mb * 4 + p * 2 + 1) * 4;
                mma_bf16(d0, aH[mb], bH[0], bH[1]);
                mma_bf16(d1, aH[mb], bH[2], bH[3]);
                mma_bf16(d0, aH[mb], bL[0], bL[1]);
                mma_bf16(d1, aH[mb], bL[2], bL[3]);
                mma_bf16(d0, aL[mb], bH[0], bH[1]);
                mma_bf16(d1, aL[mb], bH[2], bH[3]);
            }
        }
    }
    __syncthreads();

    const float* winv = (const float*)(sm + OFF_WINV);
    float* ps = (float*)(sm + OFF_PS);
    const int r0 = m0 + (lane >> 2);
    int labr[4];
    #pragma unroll
    for (int i = 0; i < 4; i++) labr[i] = g_label[r0 + (i >> 1) * 16 + (i & 1) * 8];

    float rsum[4] = {0.f, 0.f, 0.f, 0.f};
    const size_t wbase = (((size_t)h * NTILE + tile) * 8 + warp) * 512;

    #pragma unroll
    for (int mb = 0; mb < 2; mb++) {
        #pragma unroll
        for (int pn = 0; pn < 4; pn++) {
            int cb = n0 + pn * 8 + (lane & 3) * 2;
            float w0 = winv[cb], w1 = winv[cb + 1];
            int cg = c0 + cb;
            uint2 pk2;
            #pragma unroll
            for (int pr = 0; pr < 2; pr++) {
                int row = r0 + mb * 16 + pr * 8;
                int lb = labr[mb * 2 + pr];
                float v0 = acc[(mb * 4 + pn) * 4 + pr * 2 + 0];
                float v1 = acc[(mb * 4 + pn) * 4 + pr * 2 + 1];
                float cos0 = v0 * w0, cos1 = v1 * w1;
                int qi0 = 0, qi1 = 0;
                if (cg < C_) {
                    float val = cos0;
                    if (cg == lb) {
                        float sn = sqrtf(fmaxf(1.f - cos0 * cos0, 0.f));
                        float ph = cos0 * COS_M - sn * SIN_M;
                        val = (cos0 > TH_) ? ph : (cos0 - MM_);
                        g_coslab[row * H_ + h] = cos0;
                    }
                    qi0 = __float2int_rn(val * QS);
                    rsum[mb * 2 + pr] += ex2a(fmaf((float)qi0, QINV2, -S2_));
                }
                if (cg + 1 < C_) {
                    float val = cos1;
                    if (cg + 1 == lb) {
                        float sn = sqrtf(fmaxf(1.f - cos1 * cos1, 0.f));
                        float ph = cos1 * COS_M - sn * SIN_M;
                        val = (cos1 > TH_) ? ph : (cos1 - MM_);
                        g_coslab[row * H_ + h] = cos1;
                    }
                    qi1 = __float2int_rn(val * QS);
                    rsum[mb * 2 + pr] += ex2a(fmaf((float)qi1, QINV2, -S2_));
                }
                uint32_t pk = ((uint32_t)(uint16_t)(short)qi0) |
                              (((uint32_t)(uint16_t)(short)qi1) << 16);
                if (pr == 0) pk2.x = pk; else pk2.y = pk;
            }
            *(uint2*)&g_Q[wbase + (size_t)(mb * 4 + pn) * 64 + lane * 2] = pk2;
        }
    }
    #pragma unroll
    for (int i = 0; i < 4; i++) {
        float v = rsum[i];
        v += __shfl_down_sync(0xffffffffu, v, 1);
        v += __shfl_down_sync(0xffffffffu, v, 2);
        if ((lane & 3) == 0)
            ps[(r0 + (i >> 1) * 16 + (i & 1) * 8) * 2 + wn] = v;
    }
    __syncthreads();
    if (tid < 128)
        g_psum[((size_t)h * NTILE_PAD + tile) * B_ + tid] = ps[tid * 2] + ps[tid * 2 + 1];
}

// ---------------- stage-1 reduction (8 chunks; transposed output) -----------
__global__ void k_sumexp1() {
    int h = blockIdx.x, ch = blockIdx.y, b = threadIdx.x;
    int t0 = ch * CHTILES;
    float s = 0.f;
    #pragma unroll
    for (int t = 0; t < CHTILES; t++)
        s += g_psum[((size_t)h * NTILE_PAD + t0 + t) * B_ + b];
    g_psum2[(b * H_ + h) * NCHUNK + ch] = s;
}

// ---------------- k_out: eighth-split (wm 0..3, mb 0..1), 128 threads -------
// grid (NTILE, 8): qy = wm*2 + mb. Warp j: wn = j&1, pn-pair = j>>1. acc[8].
__global__ __launch_bounds__(128, 12) void k_out(float* __restrict__ out, int write_loss) {
    __shared__ float invs[128];
    __shared__ float red[128];
    const int tid = threadIdx.x, warp = tid >> 5, lane = tid & 31;
    const int tile = blockIdx.x, qy = blockIdx.y, c0 = tile * TILE_C;
    const int wm = qy >> 1, mb = qy & 1;          // wm 0..3, mb 0..1
    const int rowbase = wm * 32 + mb * 16;

    // fold invsum for THIS block's 16 rows x 8 heads: one entry per thread
    {
        const float4* p = (const float4*)&g_psum2[(rowbase * H_ + tid) * NCHUNK];
        float4 a = p[0], b4 = p[1];
        invs[tid] = 1.0f / (((a.x + a.y) + (a.z + a.w)) + ((b4.x + b4.y) + (b4.z + b4.w)));
    }
    __syncthreads();

    // block (0,0) additionally computes the NLL loss over all 1024 samples
    if (blockIdx.x == 0 && qy == 0) {
        float nll = 0.f;
        #pragma unroll
        for (int i = 0; i < 8; i++) {
            int idx = tid + 128 * i;              // b*8+h
            const float4* p = (const float4*)&g_psum2[idx * NCHUNK];
            float4 a = p[0], b4 = p[1];
            float ssum = ((a.x + a.y) + (a.z + a.w)) + ((b4.x + b4.y) + (b4.z + b4.w));
            float cos = g_coslab[idx];
            float sn = sqrtf(fmaxf(1.0f - cos * cos, 0.0f));
            float ph = cos * COS_M - sn * SIN_M;
            float val = (cos > TH_) ? ph : (cos - MM_);
            nll += -(S_ * val - S_ - logf(ssum));
        }
        red[tid] = nll;
        __syncthreads();
        #pragma unroll
        for (int st = 64; st > 0; st >>= 1) {
            if (tid < st) red[tid] += red[tid + st];
            __syncthreads();
        }
        if (tid == 0 && write_loss)
            out[(size_t)B_ * C_] = red[0] * (1.0f / (B_ * H_));
    }

    const int wn = warp & 1, png = warp >> 1;
    const int wrid = wm * 2 + wn;                 // writer warp id in pass1
    const int lr = lane >> 2;                     // local row 0..7
    const int n0 = wn * 32;

    float acc[8];
    #pragma unroll
    for (int i = 0; i < 8; i++) acc[i] = 0.f;

    for (int h = 0; h < H_; h++) {
        const uint32_t* Qp = g_Q + (((size_t)h * NTILE + tile) * 8 + wrid) * 512;
        float s0 = invs[lr * H_ + h];             // row rowbase+lr
        float s1 = invs[(lr + 8) * H_ + h];       // row rowbase+lr+8
        #pragma unroll
        for (int pj = 0; pj < 2; pj++) {
            int pn = png * 2 + pj;
            uint2 pk2 = *(const uint2*)&Qp[(size_t)(mb * 4 + pn) * 64 + lane * 2];
            #pragma unroll
            for (int pr = 0; pr < 2; pr++) {
                uint32_t pk = pr ? pk2.y : pk2.x;
                float q0 = (float)(short)(pk & 0xFFFFu);
                float q1 = (float)(short)(pk >> 16);
                float sv = pr ? s1 : s0;
                float e0 = ex2a(fmaf(q0, QINV2, -S2K_));
                float e1 = ex2a(fmaf(q1, QINV2, -S2K_));
                int ai = pj * 4 + pr * 2;
                acc[ai]     = fmaf(e0, sv, acc[ai]);
                acc[ai + 1] = fmaf(e1, sv, acc[ai + 1]);
            }
        }
    }
    // direct stores: each quad covers a contiguous 32B sector per row
    #pragma unroll
    for (int pj = 0; pj < 2; pj++)
        #pragma unroll
        for (int pr = 0; pr < 2; pr++) {
            int row = rowbase + lr + pr * 8;
            int cg = c0 + n0 + (png * 2 + pj) * 8 + (lane & 3) * 2;
            int ai = pj * 4 + pr * 2;
            if (cg + 1 < C_) {
                *(float2*)&out[(size_t)row * C_ + cg] = make_float2(acc[ai], acc[ai + 1]);
            } else if (cg < C_) {
                out[(size_t)row * C_ + cg] = acc[ai];
            }
        }
}

// ---------------- launcher ----------------
extern "C" void kernel_launch(void* const* d_in, const int* in_sizes, int n_in,
                              void* d_out, int out_size) {
    const float* x = (const float*)d_in[0];
    const float* w = (const float*)d_in[1];
    const int*   lab = (const int*)d_in[2];
    float* out = (float*)d_out;
    (void)in_sizes; (void)n_in;

    static int inited = 0;
    if (!inited) {
        cudaFuncSetAttribute(k_pass1, cudaFuncAttributeMaxDynamicSharedMemorySize, SMEM1);
        inited = 1;
    }
    int write_loss = (out_size > B_ * C_) ? 1 : 0;

    k_xnorm<<<B_, D_>>>(x, lab);
    {
        dim3 g1(NTILE, H_);
        k_pass1<<<g1, 256, SMEM1>>>(w);
    }
    {
        dim3 g2(H_, NCHUNK);
        k_sumexp1<<<g2, B_>>>();
    }
    {
        dim3 g3(NTILE, 8);
        k_out<<<g3, 128>>>(out, write_loss);
    }
}

// round 16
// speedup vs baseline: 1.0604x; 1.0145x over previous
#include <cuda_runtime.h>
#include <cuda_bf16.h>
#include <math.h>
#include <stdint.h>
#include <stddef.h>

#define B_ 128
#define H_ 8
#define DK 64
#define C_ 50000
#define D_ 512
#define TILE_C 64
#define NTILE 782          // 782*64 = 50048 >= 50000
#define NTILE_PAD 800
#define NCHUNK 8
#define CHTILES 100        // 8*100 = 800 == NTILE_PAD

#define COS_M 0.9800665778412416f
#define SIN_M 0.19866933079506122f
#define TH_  (-0.9800665778412416f)
#define MM_  0.039733866159012244f
#define S_   30.0f
#define QS   31500.0f
#define QINV2 1.3739952770371081e-3f
#define S2_   43.280851226668902f
#define S2K_  46.280851226668902f     // 1/8 head-mean folded into exponent

// ---- pass1 smem layout (bytes) ----
#define OFF_AH 0
#define OFF_AL 16384
#define OFF_BH 32768
#define OFF_BL 40960
#define OFF_WINV 49152     // 64 floats
#define OFF_WP   49408     // 256 floats
#define OFF_PS   50432     // 256 floats
#define SMEM1    51456

// ---------------- device scratch ----------------
__device__ __align__(16) __nv_bfloat16 g_Asw[H_ * 16384];
__device__ uint32_t g_Q[(size_t)H_ * NTILE * 8 * 512];      // 102MB
__device__ float g_psum[H_ * NTILE_PAD * B_];
__device__ __align__(16) float g_psum2[B_ * H_ * NCHUNK];   // [(b*8+h)][chunk]
__device__ float g_coslab[B_ * H_];
__device__ int   g_label[B_];

// ---------------- helpers ----------------
__device__ __forceinline__ uint32_t smem_u32(const void* p) {
    uint32_t a;
    asm("{ .reg .u64 t; cvta.to.shared.u64 t, %1; cvt.u32.u64 %0, t; }" : "=r"(a) : "l"(p));
    return a;
}
__device__ __forceinline__ unsigned swz(unsigned by) { return by ^ ((by >> 3) & 0x70); }
__device__ __forceinline__ float ex2a(float x) {
    float y;
    asm("ex2.approx.f32 %0, %1;" : "=f"(y) : "f"(x));
    return y;
}
__device__ __forceinline__ void ldsm4(uint32_t* r, uint32_t addr) {
    asm volatile("ldmatrix.sync.aligned.m8n8.x4.shared.b16 {%0,%1,%2,%3}, [%4];"
                 : "=r"(r[0]), "=r"(r[1]), "=r"(r[2]), "=r"(r[3]) : "r"(addr));
}
__device__ __forceinline__ void mma_bf16(float* d, const uint32_t* a, uint32_t b0, uint32_t b1) {
    asm volatile("mma.sync.aligned.m16n8k16.row.col.f32.bf16.bf16.f32 "
                 "{%0,%1,%2,%3}, {%4,%5,%6,%7}, {%8,%9}, {%0,%1,%2,%3};"
                 : "+f"(d[0]), "+f"(d[1]), "+f"(d[2]), "+f"(d[3])
                 : "r"(a[0]), "r"(a[1]), "r"(a[2]), "r"(a[3]), "r"(b0), "r"(b1));
}
__device__ __forceinline__ uint32_t cvt_bf16x2(float a, float b) {
    uint32_t r;
    asm("cvt.rn.bf16x2.f32 %0, %1, %2;" : "=r"(r) : "f"(b), "f"(a));
    return r;
}

// ---------------- xnorm (+ label decode in block 0) ----------------
__global__ void k_xnorm(const float* __restrict__ x, const int* __restrict__ raw) {
    __shared__ float wpz[16];
    __shared__ int is64;
    int b = blockIdx.x, t = threadIdx.x;
    if (b == 0 && t == 0) {
        int acc = 0;
        #pragma unroll
        for (int i = 0; i < 64; i++) acc |= raw[2 * i + 1];
        is64 = (acc == 0);
    }
    float v = x[b * D_ + t];
    float s = v * v;
    #pragma unroll
    for (int o = 16; o > 0; o >>= 1) s += __shfl_down_sync(0xffffffffu, s, o);
    if ((t & 31) == 0) wpz[t >> 5] = s;
    __syncthreads();
    if (b == 0 && t < 128) g_label[t] = is64 ? raw[2 * t] : raw[t];
    int h = t >> 6, k = t & 63;
    float ss = wpz[2 * h] + wpz[2 * h + 1];
    float xn = v * (1.0f / fmaxf(sqrtf(ss), 1e-12f));
    __nv_bfloat16 hi = __float2bfloat16(xn);
    __nv_bfloat16 lo = __float2bfloat16(xn - __bfloat162float(hi));
    unsigned by = (unsigned)b * 128u + 2u * (unsigned)k;
    unsigned sw = swz(by);
    g_Asw[h * 16384 + (sw >> 1)] = hi;
    g_Asw[h * 16384 + 8192 + (sw >> 1)] = lo;
}

// ---------------- pass1 phases (templated on full-tile) ----------------
template<bool FULL>
__device__ __forceinline__ void convert_B(const float* __restrict__ w, int h, int c0,
                                          char* sm, int tid) {
    int c = tid & 63, kg = tid >> 6;
    int cg = c0 + c;
    bool valid = FULL || (cg < C_);
    const float* wp0 = w + ((size_t)(h * DK + kg * 16)) * C_ + cg;
    float ss = 0.f;
    #pragma unroll
    for (int i = 0; i < 8; i++) {
        float v0 = valid ? __ldg(wp0 + (size_t)(2 * i) * C_) : 0.f;
        float v1 = valid ? __ldg(wp0 + (size_t)(2 * i + 1) * C_) : 0.f;
        ss = fmaf(v0, v0, ss); ss = fmaf(v1, v1, ss);
        uint32_t hpk = cvt_bf16x2(v0, v1);
        float r0 = v0 - __uint_as_float(hpk << 16);
        float r1 = v1 - __uint_as_float(hpk & 0xFFFF0000u);
        uint32_t lpk = cvt_bf16x2(r0, r1);
        unsigned by = (unsigned)c * 128u + (unsigned)(kg * 32 + 4 * i);
        unsigned sw = swz(by);
        *(uint32_t*)(sm + OFF_BH + sw) = hpk;
        *(uint32_t*)(sm + OFF_BL + sw) = lpk;
    }
    ((float*)(sm + OFF_WP))[c * 4 + kg] = ss;
}

template<bool FULL>
__device__ __forceinline__ void epilogue(char* sm, const float* acc, const int* labr,
                                         int c0, int h, int tile, int warp, int lane,
                                         int n0, int r0, int wn, float* rsum) {
    const float* winv = (const float*)(sm + OFF_WINV);
    const size_t wbase = (((size_t)h * NTILE + tile) * 8 + warp) * 512;
    #pragma unroll
    for (int mb = 0; mb < 2; mb++) {
        #pragma unroll
        for (int pn = 0; pn < 4; pn++) {
            int cb = n0 + pn * 8 + (lane & 3) * 2;
            float w0 = winv[cb], w1 = winv[cb + 1];
            int cg = c0 + cb;
            uint2 pk2;
            #pragma unroll
            for (int pr = 0; pr < 2; pr++) {
                int row = r0 + mb * 16 + pr * 8;
                int lb = labr[mb * 2 + pr];
                float v0 = acc[(mb * 4 + pn) * 4 + pr * 2 + 0];
                float v1 = acc[(mb * 4 + pn) * 4 + pr * 2 + 1];
                float cos0 = v0 * w0, cos1 = v1 * w1;
                int qi0 = 0, qi1 = 0;
                if (FULL || cg < C_) {
                    float val = cos0;
                    if (cg == lb) {
                        float sn = sqrtf(fmaxf(1.f - cos0 * cos0, 0.f));
                        float ph = cos0 * COS_M - sn * SIN_M;
                        val = (cos0 > TH_) ? ph : (cos0 - MM_);
                        g_coslab[row * H_ + h] = cos0;
                    }
                    float qf = rintf(val * QS);
                    qi0 = (int)qf;
                    rsum[mb * 2 + pr] += ex2a(fmaf(qf, QINV2, -S2_));
                }
                if (FULL || cg + 1 < C_) {
                    float val = cos1;
                    if (cg + 1 == lb) {
                        float sn = sqrtf(fmaxf(1.f - cos1 * cos1, 0.f));
                        float ph = cos1 * COS_M - sn * SIN_M;
                        val = (cos1 > TH_) ? ph : (cos1 - MM_);
                        g_coslab[row * H_ + h] = cos1;
                    }
                    float qf = rintf(val * QS);
                    qi1 = (int)qf;
                    rsum[mb * 2 + pr] += ex2a(fmaf(qf, QINV2, -S2_));
                }
                uint32_t pk = ((uint32_t)(uint16_t)(short)qi0) |
                              (((uint32_t)(uint16_t)(short)qi1) << 16);
                if (pr == 0) pk2.x = pk; else pk2.y = pk;
            }
            *(uint2*)&g_Q[wbase + (size_t)(mb * 4 + pn) * 64 + lane * 2] = pk2;
        }
    }
}

// ---------------- pass1: GEMM + margin + quantize + partial sums -------------
__global__ __launch_bounds__(256, 3) void k_pass1(const float* __restrict__ w) {
    extern __shared__ char sm[];
    const int tid = threadIdx.x, warp = tid >> 5, lane = tid & 31;
    const int h = blockIdx.y, tile = blockIdx.x, c0 = tile * TILE_C;
    uint32_t sb = smem_u32(sm);
    const bool full = (c0 + TILE_C <= C_);

    {
        const uint4* src = (const uint4*)(g_Asw + h * 16384);
        uint4* dst = (uint4*)(sm + OFF_AH);
        #pragma unroll
        for (int i = 0; i < 8; i++) dst[tid + 256 * i] = src[tid + 256 * i];
    }
    if (full) convert_B<true>(w, h, c0, sm, tid);
    else      convert_B<false>(w, h, c0, sm, tid);
    __syncthreads();
    if (tid < 64) {
        float* wp = (float*)(sm + OFF_WP);
        ((float*)(sm + OFF_WINV))[tid] =
            1.0f / fmaxf(sqrtf(wp[tid * 4] + wp[tid * 4 + 1] + wp[tid * 4 + 2] + wp[tid * 4 + 3]),
                         1e-12f);
    }

    const int wm = warp >> 1, wn = warp & 1;
    const int m0 = wm * 32, n0 = wn * 32;
    const int lrow = lane & 7, lt = lane >> 3;
    const int rowAo = lrow + (lt & 1) * 8;
    const int kbAo = (lt >> 1) * 16;
    const int rowBo = lrow + (lt >> 1) * 8;
    const int kbBo = (lt & 1) * 16;

    float acc[32];
    #pragma unroll
    for (int i = 0; i < 32; i++) acc[i] = 0.f;

    #pragma unroll
    for (int ks = 0; ks < 4; ks++) {
        uint32_t aH[2][4], aL[2][4];
        #pragma unroll
        for (int mb = 0; mb < 2; mb++) {
            unsigned sw = swz((unsigned)((m0 + mb * 16 + rowAo) * 128 + ks * 32 + kbAo));
            ldsm4(aH[mb], sb + OFF_AH + sw);
            ldsm4(aL[mb], sb + OFF_AL + sw);
        }
        #pragma unroll
        for (int p = 0; p < 2; p++) {
            unsigned sw = swz((unsigned)((n0 + p * 16 + rowBo) * 128 + ks * 32 + kbBo));
            uint32_t bH[4], bL[4];
            ldsm4(bH, sb + OFF_BH + sw);
            ldsm4(bL, sb + OFF_BL + sw);
            #pragma unroll
            for (int mb = 0; mb < 2; mb++) {
                float* d0 = acc + (mb * 4 + p * 2) * 4;
                float* d1 = acc + (mb * 4 + p * 2 + 1) * 4;
                mma_bf16(d0, aH[mb], bH[0], bH[1]);
                mma_bf16(d1, aH[mb], bH[2], bH[3]);
                mma_bf16(d0, aH[mb], bL[0], bL[1]);
                mma_bf16(d1, aH[mb], bL[2], bL[3]);
                mma_bf16(d0, aL[mb], bH[0], bH[1]);
                mma_bf16(d1, aL[mb], bH[2], bH[3]);
            }
        }
    }
    __syncthreads();

    float* ps = (float*)(sm + OFF_PS);
    const int r0 = m0 + (lane >> 2);
    int labr[4];
    #pragma unroll
    for (int i = 0; i < 4; i++) labr[i] = g_label[r0 + (i >> 1) * 16 + (i & 1) * 8];

    float rsum[4] = {0.f, 0.f, 0.f, 0.f};
    if (full) epilogue<true>(sm, acc, labr, c0, h, tile, warp, lane, n0, r0, wn, rsum);
    else      epilogue<false>(sm, acc, labr, c0, h, tile, warp, lane, n0, r0, wn, rsum);

    #pragma unroll
    for (int i = 0; i < 4; i++) {
        float v = rsum[i];
        v += __shfl_down_sync(0xffffffffu, v, 1);
        v += __shfl_down_sync(0xffffffffu, v, 2);
        if ((lane & 3) == 0)
            ps[(r0 + (i >> 1) * 16 + (i & 1) * 8) * 2 + wn] = v;
    }
    __syncthreads();
    if (tid < 128)
        g_psum[((size_t)h * NTILE_PAD + tile) * B_ + tid] = ps[tid * 2] + ps[tid * 2 + 1];
}

// ---------------- stage-1 reduction (8 chunks; transposed output) -----------
__global__ void k_sumexp1() {
    int h = blockIdx.x, ch = blockIdx.y, b = threadIdx.x;
    int t0 = ch * CHTILES;
    float s = 0.f;
    #pragma unroll
    for (int t = 0; t < CHTILES; t++)
        s += g_psum[((size_t)h * NTILE_PAD + t0 + t) * B_ + b];
    g_psum2[(b * H_ + h) * NCHUNK + ch] = s;
}

// ---------------- k_out: eighth-split (wm 0..3, mb 0..1), 128 threads -------
__global__ __launch_bounds__(128, 12) void k_out(float* __restrict__ out, int write_loss) {
    __shared__ float invs[128];
    __shared__ float red[128];
    const int tid = threadIdx.x, warp = tid >> 5, lane = tid & 31;
    const int tile = blockIdx.x, qy = blockIdx.y, c0 = tile * TILE_C;
    const int wm = qy >> 1, mb = qy & 1;          // wm 0..3, mb 0..1
    const int rowbase = wm * 32 + mb * 16;

    {
        const float4* p = (const float4*)&g_psum2[(rowbase * H_ + tid) * NCHUNK];
        float4 a = p[0], b4 = p[1];
        invs[tid] = 1.0f / (((a.x + a.y) + (a.z + a.w)) + ((b4.x + b4.y) + (b4.z + b4.w)));
    }
    __syncthreads();

    if (blockIdx.x == 0 && qy == 0) {
        float nll = 0.f;
        #pragma unroll
        for (int i = 0; i < 8; i++) {
            int idx = tid + 128 * i;              // b*8+h
            const float4* p = (const float4*)&g_psum2[idx * NCHUNK];
            float4 a = p[0], b4 = p[1];
            float ssum = ((a.x + a.y) + (a.z + a.w)) + ((b4.x + b4.y) + (b4.z + b4.w));
            float cos = g_coslab[idx];
            float sn = sqrtf(fmaxf(1.0f - cos * cos, 0.0f));
            float ph = cos * COS_M - sn * SIN_M;
            float val = (cos > TH_) ? ph : (cos - MM_);
            nll += -(S_ * val - S_ - logf(ssum));
        }
        red[tid] = nll;
        __syncthreads();
        #pragma unroll
        for (int st = 64; st > 0; st >>= 1) {
            if (tid < st) red[tid] += red[tid + st];
            __syncthreads();
        }
        if (tid == 0 && write_loss)
            out[(size_t)B_ * C_] = red[0] * (1.0f / (B_ * H_));
    }

    const int wn = warp & 1, png = warp >> 1;
    const int wrid = wm * 2 + wn;                 // writer warp id in pass1
    const int lr = lane >> 2;                     // local row 0..7
    const int n0 = wn * 32;

    float acc[8];
    #pragma unroll
    for (int i = 0; i < 8; i++) acc[i] = 0.f;

    #pragma unroll 2
    for (int h = 0; h < H_; h++) {
        const uint32_t* Qp = g_Q + (((size_t)h * NTILE + tile) * 8 + wrid) * 512;
        float s0 = invs[lr * H_ + h];             // row rowbase+lr
        float s1 = invs[(lr + 8) * H_ + h];       // row rowbase+lr+8
        #pragma unroll
        for (int pj = 0; pj < 2; pj++) {
            int pn = png * 2 + pj;
            uint2 pk2 = *(const uint2*)&Qp[(size_t)(mb * 4 + pn) * 64 + lane * 2];
            #pragma unroll
            for (int pr = 0; pr < 2; pr++) {
                uint32_t pk = pr ? pk2.y : pk2.x;
                float q0 = (float)(short)(pk & 0xFFFFu);
                float q1 = (float)(short)(pk >> 16);
                float sv = pr ? s1 : s0;
                float e0 = ex2a(fmaf(q0, QINV2, -S2K_));
                float e1 = ex2a(fmaf(q1, QINV2, -S2K_));
                int ai = pj * 4 + pr * 2;
                acc[ai]     = fmaf(e0, sv, acc[ai]);
                acc[ai + 1] = fmaf(e1, sv, acc[ai + 1]);
            }
        }
    }
    #pragma unroll
    for (int pj = 0; pj < 2; pj++)
        #pragma unroll
        for (int pr = 0; pr < 2; pr++) {
            int row = rowbase + lr + pr * 8;
            int cg = c0 + n0 + (png * 2 + pj) * 8 + (lane & 3) * 2;
            int ai = pj * 4 + pr * 2;
            if (cg + 1 < C_) {
                *(float2*)&out[(size_t)row * C_ + cg] = make_float2(acc[ai], acc[ai + 1]);
            } else if (cg < C_) {
                out[(size_t)row * C_ + cg] = acc[ai];
            }
        }
}

// ---------------- launcher ----------------
extern "C" void kernel_launch(void* const* d_in, const int* in_sizes, int n_in,
                              void* d_out, int out_size) {
    const float* x = (const float*)d_in[0];
    const float* w = (const float*)d_in[1];
    const int*   lab = (const int*)d_in[2];
    float* out = (float*)d_out;
    (void)in_sizes; (void)n_in;

    static int inited = 0;
    if (!inited) {
        cudaFuncSetAttribute(k_pass1, cudaFuncAttributeMaxDynamicSharedMemorySize, SMEM1);
        inited = 1;
    }
    int write_loss = (out_size > B_ * C_) ? 1 : 0;

    k_xnorm<<<B_, D_>>>(x, lab);
    {
        dim3 g1(NTILE, H_);
        k_pass1<<<g1, 256, SMEM1>>>(w);
    }
    {
        dim3 g2(H_, NCHUNK);
        k_sumexp1<<<g2, B_>>>();
    }
    {
        dim3 g3(NTILE, 8);
        k_out<<<g3, 128>>>(out, write_loss);
    }
}

// round 17
// speedup vs baseline: 1.0606x; 1.0002x over previous
#include <cuda_runtime.h>
#include <cuda_bf16.h>
#include <math.h>
#include <stdint.h>
#include <stddef.h>

#define B_ 128
#define H_ 8
#define DK 64
#define C_ 50000
#define D_ 512
#define TILE_C 64
#define NTILE 782          // 782*64 = 50048 >= 50000
#define NTILE_PAD 800
#define NCHUNK 8
#define CHTILES 100        // 8*100 = 800 == NTILE_PAD

#define COS_M 0.9800665778412416f
#define SIN_M 0.19866933079506122f
#define TH_  (-0.9800665778412416f)
#define MM_  0.039733866159012244f
#define S_   30.0f
#define QS   31500.0f
#define QINV2 1.3739952770371081e-3f
#define S2_   43.280851226668902f
#define S2K_  46.280851226668902f     // 1/8 head-mean folded into exponent

// ---- pass1 smem layout (bytes) ----
#define OFF_AH 0
#define OFF_AL 16384
#define OFF_BH 32768
#define OFF_BL 40960
#define OFF_WINV 49152     // 64 floats
#define OFF_WP   49408     // 256 floats
#define OFF_PS   50432     // 256 floats
#define SMEM1    51456

// ---------------- device scratch ----------------
__device__ __align__(16) __nv_bfloat16 g_Asw[H_ * 16384];
__device__ __align__(16) uint32_t g_Q[(size_t)H_ * NTILE * 8 * 512];  // 102MB
__device__ float g_psum[H_ * NTILE_PAD * B_];
__device__ __align__(16) float g_psum2[B_ * H_ * NCHUNK];   // [(b*8+h)][chunk]
__device__ float g_coslab[B_ * H_];
__device__ int   g_label[B_];

// ---------------- helpers ----------------
__device__ __forceinline__ uint32_t smem_u32(const void* p) {
    uint32_t a;
    asm("{ .reg .u64 t; cvta.to.shared.u64 t, %1; cvt.u32.u64 %0, t; }" : "=r"(a) : "l"(p));
    return a;
}
__device__ __forceinline__ unsigned swz(unsigned by) { return by ^ ((by >> 3) & 0x70); }
__device__ __forceinline__ float ex2a(float x) {
    float y;
    asm("ex2.approx.f32 %0, %1;" : "=f"(y) : "f"(x));
    return y;
}
__device__ __forceinline__ void ldsm4(uint32_t* r, uint32_t addr) {
    asm volatile("ldmatrix.sync.aligned.m8n8.x4.shared.b16 {%0,%1,%2,%3}, [%4];"
                 : "=r"(r[0]), "=r"(r[1]), "=r"(r[2]), "=r"(r[3]) : "r"(addr));
}
__device__ __forceinline__ void mma_bf16(float* d, const uint32_t* a, uint32_t b0, uint32_t b1) {
    asm volatile("mma.sync.aligned.m16n8k16.row.col.f32.bf16.bf16.f32 "
                 "{%0,%1,%2,%3}, {%4,%5,%6,%7}, {%8,%9}, {%0,%1,%2,%3};"
                 : "+f"(d[0]), "+f"(d[1]), "+f"(d[2]), "+f"(d[3])
                 : "r"(a[0]), "r"(a[1]), "r"(a[2]), "r"(a[3]), "r"(b0), "r"(b1));
}
__device__ __forceinline__ uint32_t cvt_bf16x2(float a, float b) {
    uint32_t r;
    asm("cvt.rn.bf16x2.f32 %0, %1, %2;" : "=r"(r) : "f"(b), "f"(a));
    return r;
}

// ---------------- xnorm (+ label decode in block 0) ----------------
__global__ void k_xnorm(const float* __restrict__ x, const int* __restrict__ raw) {
    __shared__ float wpz[16];
    __shared__ int is64;
    int b = blockIdx.x, t = threadIdx.x;
    if (b == 0 && t == 0) {
        int acc = 0;
        #pragma unroll
        for (int i = 0; i < 64; i++) acc |= raw[2 * i + 1];
        is64 = (acc == 0);
    }
    float v = x[b * D_ + t];
    float s = v * v;
    #pragma unroll
    for (int o = 16; o > 0; o >>= 1) s += __shfl_down_sync(0xffffffffu, s, o);
    if ((t & 31) == 0) wpz[t >> 5] = s;
    __syncthreads();
    if (b == 0 && t < 128) g_label[t] = is64 ? raw[2 * t] : raw[t];
    int h = t >> 6, k = t & 63;
    float ss = wpz[2 * h] + wpz[2 * h + 1];
    float xn = v * (1.0f / fmaxf(sqrtf(ss), 1e-12f));
    __nv_bfloat16 hi = __float2bfloat16(xn);
    __nv_bfloat16 lo = __float2bfloat16(xn - __bfloat162float(hi));
    unsigned by = (unsigned)b * 128u + 2u * (unsigned)k;
    unsigned sw = swz(by);
    g_Asw[h * 16384 + (sw >> 1)] = hi;
    g_Asw[h * 16384 + 8192 + (sw >> 1)] = lo;
}

// ---------------- pass1 phases (templated on full-tile) ----------------
template<bool FULL>
__device__ __forceinline__ void convert_B(const float* __restrict__ w, int h, int c0,
                                          char* sm, int tid) {
    int c = tid & 63, kg = tid >> 6;
    int cg = c0 + c;
    bool valid = FULL || (cg < C_);
    const float* wp0 = w + ((size_t)(h * DK + kg * 16)) * C_ + cg;
    float ss = 0.f;
    #pragma unroll
    for (int i = 0; i < 8; i++) {
        float v0 = valid ? __ldg(wp0 + (size_t)(2 * i) * C_) : 0.f;
        float v1 = valid ? __ldg(wp0 + (size_t)(2 * i + 1) * C_) : 0.f;
        ss = fmaf(v0, v0, ss); ss = fmaf(v1, v1, ss);
        uint32_t hpk = cvt_bf16x2(v0, v1);
        float r0 = v0 - __uint_as_float(hpk << 16);
        float r1 = v1 - __uint_as_float(hpk & 0xFFFF0000u);
        uint32_t lpk = cvt_bf16x2(r0, r1);
        unsigned by = (unsigned)c * 128u + (unsigned)(kg * 32 + 4 * i);
        unsigned sw = swz(by);
        *(uint32_t*)(sm + OFF_BH + sw) = hpk;
        *(uint32_t*)(sm + OFF_BL + sw) = lpk;
    }
    ((float*)(sm + OFF_WP))[c * 4 + kg] = ss;
}

// uint4 Q layout: per (mb, png) block of 128 uint32; lane holds 4 consecutive:
// [pj0pr0, pj0pr1, pj1pr0, pj1pr1]
template<bool FULL>
__device__ __forceinline__ void epilogue(char* sm, const float* acc, const int* labr,
                                         int c0, int h, int tile, int warp, int lane,
                                         int n0, int r0, int wn, float* rsum) {
    const float* winv = (const float*)(sm + OFF_WINV);
    const size_t wbase = (((size_t)h * NTILE + tile) * 8 + warp) * 512;
    #pragma unroll
    for (int mb = 0; mb < 2; mb++) {
        #pragma unroll
        for (int png = 0; png < 2; png++) {
            uint4 pk4;
            #pragma unroll
            for (int pj = 0; pj < 2; pj++) {
                int pn = png * 2 + pj;
                int cb = n0 + pn * 8 + (lane & 3) * 2;
                float w0 = winv[cb], w1 = winv[cb + 1];
                int cg = c0 + cb;
                #pragma unroll
                for (int pr = 0; pr < 2; pr++) {
                    int row = r0 + mb * 16 + pr * 8;
                    int lb = labr[mb * 2 + pr];
                    float v0 = acc[(mb * 4 + pn) * 4 + pr * 2 + 0];
                    float v1 = acc[(mb * 4 + pn) * 4 + pr * 2 + 1];
                    float cos0 = v0 * w0, cos1 = v1 * w1;
                    int qi0 = 0, qi1 = 0;
                    if (FULL || cg < C_) {
                        float val = cos0;
                        if (cg == lb) {
                            float sn = sqrtf(fmaxf(1.f - cos0 * cos0, 0.f));
                            float ph = cos0 * COS_M - sn * SIN_M;
                            val = (cos0 > TH_) ? ph : (cos0 - MM_);
                            g_coslab[row * H_ + h] = cos0;
                        }
                        float qf = rintf(val * QS);
                        qi0 = (int)qf;
                        rsum[mb * 2 + pr] += ex2a(fmaf(qf, QINV2, -S2_));
                    }
                    if (FULL || cg + 1 < C_) {
                        float val = cos1;
                        if (cg + 1 == lb) {
                            float sn = sqrtf(fmaxf(1.f - cos1 * cos1, 0.f));
                            float ph = cos1 * COS_M - sn * SIN_M;
                            val = (cos1 > TH_) ? ph : (cos1 - MM_);
                            g_coslab[row * H_ + h] = cos1;
                        }
                        float qf = rintf(val * QS);
                        qi1 = (int)qf;
                        rsum[mb * 2 + pr] += ex2a(fmaf(qf, QINV2, -S2_));
                    }
                    uint32_t pk = ((uint32_t)(uint16_t)(short)qi0) |
                                  (((uint32_t)(uint16_t)(short)qi1) << 16);
                    if (pj == 0) { if (pr == 0) pk4.x = pk; else pk4.y = pk; }
                    else         { if (pr == 0) pk4.z = pk; else pk4.w = pk; }
                }
            }
            *(uint4*)&g_Q[wbase + (size_t)(mb * 2 + png) * 128 + lane * 4] = pk4;
        }
    }
}

// ---------------- pass1: GEMM + margin + quantize + partial sums -------------
__global__ __launch_bounds__(256, 3) void k_pass1(const float* __restrict__ w) {
    extern __shared__ char sm[];
    const int tid = threadIdx.x, warp = tid >> 5, lane = tid & 31;
    const int h = blockIdx.y, tile = blockIdx.x, c0 = tile * TILE_C;
    uint32_t sb = smem_u32(sm);
    const bool full = (c0 + TILE_C <= C_);

    {
        const uint4* src = (const uint4*)(g_Asw + h * 16384);
        uint4* dst = (uint4*)(sm + OFF_AH);
        #pragma unroll
        for (int i = 0; i < 8; i++) dst[tid + 256 * i] = src[tid + 256 * i];
    }
    if (full) convert_B<true>(w, h, c0, sm, tid);
    else      convert_B<false>(w, h, c0, sm, tid);
    __syncthreads();
    if (tid < 64) {
        float* wp = (float*)(sm + OFF_WP);
        ((float*)(sm + OFF_WINV))[tid] =
            1.0f / fmaxf(sqrtf(wp[tid * 4] + wp[tid * 4 + 1] + wp[tid * 4 + 2] + wp[tid * 4 + 3]),
                         1e-12f);
    }

    const int wm = warp >> 1, wn = warp & 1;
    const int m0 = wm * 32, n0 = wn * 32;
    const int lrow = lane & 7, lt = lane >> 3;
    const int rowAo = lrow + (lt & 1) * 8;
    const int kbAo = (lt >> 1) * 16;
    const int rowBo = lrow + (lt >> 1) * 8;
    const int kbBo = (lt & 1) * 16;

    float acc[32];
    #pragma unroll
    for (int i = 0; i < 32; i++) acc[i] = 0.f;

    #pragma unroll
    for (int ks = 0; ks < 4; ks++) {
        uint32_t aH[2][4], aL[2][4];
        #pragma unroll
        for (int mb = 0; mb < 2; mb++) {
            unsigned sw = swz((unsigned)((m0 + mb * 16 + rowAo) * 128 + ks * 32 + kbAo));
            ldsm4(aH[mb], sb + OFF_AH + sw);
            ldsm4(aL[mb], sb + OFF_AL + sw);
        }
        #pragma unroll
        for (int p = 0; p < 2; p++) {
            unsigned sw = swz((unsigned)((n0 + p * 16 + rowBo) * 128 + ks * 32 + kbBo));
            uint32_t bH[4], bL[4];
            ldsm4(bH, sb + OFF_BH + sw);
            ldsm4(bL, sb + OFF_BL + sw);
            #pragma unroll
            for (int mb = 0; mb < 2; mb++) {
                float* d0 = acc + (mb * 4 + p * 2) * 4;
                float* d1 = acc + (mb * 4 + p * 2 + 1) * 4;
                mma_bf16(d0, aH[mb], bH[0], bH[1]);
                mma_bf16(d1, aH[mb], bH[2], bH[3]);
                mma_bf16(d0, aH[mb], bL[0], bL[1]);
                mma_bf16(d1, aH[mb], bL[2], bL[3]);
                mma_bf16(d0, aL[mb], bH[0], bH[1]);
                mma_bf16(d1, aL[mb], bH[2], bH[3]);
            }
        }
    }
    __syncthreads();

    float* ps = (float*)(sm + OFF_PS);
    const int r0 = m0 + (lane >> 2);
    int labr[4];
    #pragma unroll
    for (int i = 0; i < 4; i++) labr[i] = g_label[r0 + (i >> 1) * 16 + (i & 1) * 8];

    float rsum[4] = {0.f, 0.f, 0.f, 0.f};
    if (full) epilogue<true>(sm, acc, labr, c0, h, tile, warp, lane, n0, r0, wn, rsum);
    else      epilogue<false>(sm, acc, labr, c0, h, tile, warp, lane, n0, r0, wn, rsum);

    #pragma unroll
    for (int i = 0; i < 4; i++) {
        float v = rsum[i];
        v += __shfl_down_sync(0xffffffffu, v, 1);
        v += __shfl_down_sync(0xffffffffu, v, 2);
        if ((lane & 3) == 0)
            ps[(r0 + (i >> 1) * 16 + (i & 1) * 8) * 2 + wn] = v;
    }
    __syncthreads();
    if (tid < 128)
        g_psum[((size_t)h * NTILE_PAD + tile) * B_ + tid] = ps[tid * 2] + ps[tid * 2 + 1];
}

// ---------------- stage-1 reduction (8 chunks; transposed output) -----------
__global__ void k_sumexp1() {
    int h = blockIdx.x, ch = blockIdx.y, b = threadIdx.x;
    int t0 = ch * CHTILES;
    float s = 0.f;
    #pragma unroll
    for (int t = 0; t < CHTILES; t++)
        s += g_psum[((size_t)h * NTILE_PAD + t0 + t) * B_ + b];
    g_psum2[(b * H_ + h) * NCHUNK + ch] = s;
}

// ---------------- k_out: eighth-split (wm 0..3, mb 0..1), 128 threads -------
__global__ __launch_bounds__(128, 12) void k_out(float* __restrict__ out, int write_loss) {
    __shared__ float invs[128];
    __shared__ float red[128];
    const int tid = threadIdx.x, warp = tid >> 5, lane = tid & 31;
    const int tile = blockIdx.x, qy = blockIdx.y, c0 = tile * TILE_C;
    const int wm = qy >> 1, mb = qy & 1;          // wm 0..3, mb 0..1
    const int rowbase = wm * 32 + mb * 16;

    {
        const float4* p = (const float4*)&g_psum2[(rowbase * H_ + tid) * NCHUNK];
        float4 a = p[0], b4 = p[1];
        invs[tid] = 1.0f / (((a.x + a.y) + (a.z + a.w)) + ((b4.x + b4.y) + (b4.z + b4.w)));
    }
    __syncthreads();

    if (blockIdx.x == 0 && qy == 0) {
        float nll = 0.f;
        #pragma unroll
        for (int i = 0; i < 8; i++) {
            int idx = tid + 128 * i;              // b*8+h
            const float4* p = (const float4*)&g_psum2[idx * NCHUNK];
            float4 a = p[0], b4 = p[1];
            float ssum = ((a.x + a.y) + (a.z + a.w)) + ((b4.x + b4.y) + (b4.z + b4.w));
            float cos = g_coslab[idx];
            float sn = sqrtf(fmaxf(1.0f - cos * cos, 0.0f));
            float ph = cos * COS_M - sn * SIN_M;
            float val = (cos > TH_) ? ph : (cos - MM_);
            nll += -(S_ * val - S_ - logf(ssum));
        }
        red[tid] = nll;
        __syncthreads();
        #pragma unroll
        for (int st = 64; st > 0; st >>= 1) {
            if (tid < st) red[tid] += red[tid + st];
            __syncthreads();
        }
        if (tid == 0 && write_loss)
            out[(size_t)B_ * C_] = red[0] * (1.0f / (B_ * H_));
    }

    const int wn = warp & 1, png = warp >> 1;
    const int wrid = wm * 2 + wn;                 // writer warp id in pass1
    const int lr = lane >> 2;                     // local row 0..7
    const int n0 = wn * 32;

    float acc[8];
    #pragma unroll
    for (int i = 0; i < 8; i++) acc[i] = 0.f;

    #pragma unroll 2
    for (int h = 0; h < H_; h++) {
        const uint32_t* Qp = g_Q + (((size_t)h * NTILE + tile) * 8 + wrid) * 512;
        float s0 = invs[lr * H_ + h];             // row rowbase+lr
        float s1 = invs[(lr + 8) * H_ + h];       // row rowbase+lr+8
        uint4 pk4 = *(const uint4*)&Qp[(size_t)(mb * 2 + png) * 128 + lane * 4];
        #pragma unroll
        for (int pj = 0; pj < 2; pj++) {
            #pragma unroll
            for (int pr = 0; pr < 2; pr++) {
                uint32_t pk = pj ? (pr ? pk4.w : pk4.z) : (pr ? pk4.y : pk4.x);
                float q0 = (float)(short)(pk & 0xFFFFu);
                float q1 = (float)(short)(pk >> 16);
                float sv = pr ? s1 : s0;
                float e0 = ex2a(fmaf(q0, QINV2, -S2K_));
                float e1 = ex2a(fmaf(q1, QINV2, -S2K_));
                int ai = pj * 4 + pr * 2;
                acc[ai]     = fmaf(e0, sv, acc[ai]);
                acc[ai + 1] = fmaf(e1, sv, acc[ai + 1]);
            }
        }
    }
    #pragma unroll
    for (int pj = 0; pj < 2; pj++)
        #pragma unroll
        for (int pr = 0; pr < 2; pr++) {
            int row = rowbase + lr + pr * 8;
            int cg = c0 + n0 + (png * 2 + pj) * 8 + (lane & 3) * 2;
            int ai = pj * 4 + pr * 2;
            if (cg + 1 < C_) {
                *(float2*)&out[(size_t)row * C_ + cg] = make_float2(acc[ai], acc[ai + 1]);
            } else if (cg < C_) {
                out[(size_t)row * C_ + cg] = acc[ai];
            }
        }
}

// ---------------- launcher ----------------
extern "C" void kernel_launch(void* const* d_in, const int* in_sizes, int n_in,
                              void* d_out, int out_size) {
    const float* x = (const float*)d_in[0];
    const float* w = (const float*)d_in[1];
    const int*   lab = (const int*)d_in[2];
    float* out = (float*)d_out;
    (void)in_sizes; (void)n_in;

    static int inited = 0;
    if (!inited) {
        cudaFuncSetAttribute(k_pass1, cudaFuncAttributeMaxDynamicSharedMemorySize, SMEM1);
        inited = 1;
    }
    int write_loss = (out_size > B_ * C_) ? 1 : 0;

    k_xnorm<<<B_, D_>>>(x, lab);
    {
        dim3 g1(NTILE, H_);
        k_pass1<<<g1, 256, SMEM1>>>(w);
    }
    {
        dim3 g2(H_, NCHUNK);
        k_sumexp1<<<g2, B_>>>();
    }
    {
        dim3 g3(NTILE, 8);
        k_out<<<g3, 128>>>(out, write_loss);
    }
}